// round 1
// baseline (speedup 1.0000x reference)
#include <cuda_runtime.h>
#include <math.h>

#define T_DATA 40000
#define SUB    32
#define E_E    2000
#define E_I    400
#define TNO    200
#define NCOS   17
#define FILT_OFF (2*T_DATA)

#define PI_F   3.14159274f      // float32(pi), matches jnp
#define HPI_F  1.5707964f       // float32(pi/2)

// ---------------- scratch (no allocation allowed) ----------------
__device__ float g_syn_e[(size_t)T_DATA*SUB];
__device__ float g_syn_i[(size_t)T_DATA*SUB];
__device__ float g_syn  [(size_t)T_DATA*SUB];
__device__ float g_ke[TNO*SUB];   // transposed [tau][s]
__device__ float g_ki[TNO*SUB];
__device__ float g_hk[TNO];
__device__ float g_ok[TNO];
__device__ float g_cw[SUB*SUB];
__device__ int   g_ecnt[E_E];
__device__ int   g_esub[E_E*SUB];
__device__ float g_ew  [E_E*SUB];
__device__ int   g_icnt[E_I];
__device__ int   g_isub[E_I*SUB];
__device__ float g_iw  [E_I*SUB];

// ---------------- K0: build per-column CSR of C_syn_e / C_syn_i ----------------
__global__ void k0_csr(const float* __restrict__ Ce, const float* __restrict__ Ci) {
    int e = blockIdx.x * blockDim.x + threadIdx.x;
    if (e < E_E) {
        int c = 0;
        for (int s = 0; s < SUB; s++) {
            float w = Ce[(size_t)s * E_E + e];
            if (w != 0.f) { g_esub[e*SUB + c] = s; g_ew[e*SUB + c] = w; c++; }
        }
        g_ecnt[e] = c;
    }
    if (e < E_I) {
        int c = 0;
        for (int s = 0; s < SUB; s++) {
            float w = Ci[(size_t)s * E_I + e];
            if (w != 0.f) { g_isub[e*SUB + c] = s; g_iw[e*SUB + c] = w; c++; }
        }
        g_icnt[e] = c;
    }
}

// ---------------- K2: all small kernels/filters + out_filters section ----------------
__global__ void k2_kernels(const float* __restrict__ Tau_syn, const float* __restrict__ Delta_syn,
                           const float* __restrict__ W_syn,   const float* __restrict__ W_sub,
                           const float* __restrict__ W_hist,  const float* __restrict__ Tau_out,
                           const float* __restrict__ W_out,   const float* __restrict__ C_den,
                           float* __restrict__ dout) {
    int tid = blockIdx.x * blockDim.x + threadIdx.x;
    int stride = blockDim.x * gridDim.x;

    for (int i = tid; i < SUB * TNO; i += stride) {
        int s = i / TNO, tau = i % TNO;
        float t = (float)tau;
        float te  = fmaxf(t - expf(Delta_syn[s*2 + 0]), 0.f);
        float tte = te / expf(Tau_syn[s*2 + 0]);
        float ek  = tte * expf(-tte) * expf(W_syn[s*2 + 0]);
        float ti  = fmaxf(t - expf(Delta_syn[s*2 + 1]), 0.f);
        float tti = ti / expf(Tau_syn[s*2 + 1]);
        float ik  = -tti * expf(-tti) * expf(W_syn[s*2 + 1]);
        g_ke[tau*SUB + s] = ek;
        g_ki[tau*SUB + s] = ik;
        dout[FILT_OFF + s*TNO + tau]              = ek;
        dout[FILT_OFF + SUB*TNO + s*TNO + tau]    = ik;
    }

    for (int tau = tid; tau < TNO; tau += stride) {
        float raw = 4.f * logf((float)tau + 1.f);
        float hk = 0.f;
        #pragma unroll
        for (int n = 0; n < NCOS; n++) {
            float phi = HPI_F * (float)n;
            if (raw >= phi - PI_F && raw <= phi + PI_F)
                hk -= expf(W_hist[n]) * (0.5f * cosf(raw - phi) + 0.5f);
        }
        g_hk[tau] = hk;
        dout[FILT_OFF + 2*SUB*TNO + tau] = hk;

        float tto = (float)tau / expf(Tau_out[0]);
        g_ok[tau] = tto * expf(-tto) * expf(W_out[0]);
    }

    for (int i = tid; i < SUB * SUB; i += stride)
        g_cw[i] = C_den[i] * expf(W_sub[i % SUB]);
}

// ---------------- K1: sparse spike projection -> syn_e / syn_i [T][32] ----------------
__global__ void k1_proj(const float* __restrict__ Se, const float* __restrict__ Si) {
    __shared__ float accE[8][SUB];
    __shared__ float accI[8][SUB];
    int wp = threadIdx.x >> 5, lane = threadIdx.x & 31;
    int t = blockIdx.x * 8 + wp;
    if (t >= T_DATA) return;

    accE[wp][lane] = 0.f;
    accI[wp][lane] = 0.f;
    __syncwarp();

    // excitatory: 2000 floats = 500 float4, coalesced per warp
    {
        const float4* p = (const float4*)(Se + (size_t)t * E_E);
        const int NQ = E_E / 4;   // 500
        #pragma unroll 4
        for (int q = lane; q < NQ; q += 32) {
            float4 v = p[q];
            int e0 = q * 4;
            if (v.x != 0.f) { int c = g_ecnt[e0+0]; for (int k=0;k<c;k++) atomicAdd(&accE[wp][g_esub[(e0+0)*SUB+k]], v.x * g_ew[(e0+0)*SUB+k]); }
            if (v.y != 0.f) { int c = g_ecnt[e0+1]; for (int k=0;k<c;k++) atomicAdd(&accE[wp][g_esub[(e0+1)*SUB+k]], v.y * g_ew[(e0+1)*SUB+k]); }
            if (v.z != 0.f) { int c = g_ecnt[e0+2]; for (int k=0;k<c;k++) atomicAdd(&accE[wp][g_esub[(e0+2)*SUB+k]], v.z * g_ew[(e0+2)*SUB+k]); }
            if (v.w != 0.f) { int c = g_ecnt[e0+3]; for (int k=0;k<c;k++) atomicAdd(&accE[wp][g_esub[(e0+3)*SUB+k]], v.w * g_ew[(e0+3)*SUB+k]); }
        }
    }
    // inhibitory: 400 floats = 100 float4
    {
        const float4* p = (const float4*)(Si + (size_t)t * E_I);
        const int NQ = E_I / 4;   // 100
        #pragma unroll 2
        for (int q = lane; q < NQ; q += 32) {
            float4 v = p[q];
            int e0 = q * 4;
            if (v.x != 0.f) { int c = g_icnt[e0+0]; for (int k=0;k<c;k++) atomicAdd(&accI[wp][g_isub[(e0+0)*SUB+k]], v.x * g_iw[(e0+0)*SUB+k]); }
            if (v.y != 0.f) { int c = g_icnt[e0+1]; for (int k=0;k<c;k++) atomicAdd(&accI[wp][g_isub[(e0+1)*SUB+k]], v.y * g_iw[(e0+1)*SUB+k]); }
            if (v.z != 0.f) { int c = g_icnt[e0+2]; for (int k=0;k<c;k++) atomicAdd(&accI[wp][g_isub[(e0+2)*SUB+k]], v.z * g_iw[(e0+2)*SUB+k]); }
            if (v.w != 0.f) { int c = g_icnt[e0+3]; for (int k=0;k<c;k++) atomicAdd(&accI[wp][g_isub[(e0+3)*SUB+k]], v.w * g_iw[(e0+3)*SUB+k]); }
        }
    }
    __syncwarp();
    g_syn_e[(size_t)t * SUB + lane] = accE[wp][lane];
    g_syn_i[(size_t)t * SUB + lane] = accI[wp][lane];
}

// ---------------- K3: depthwise causal conv (200 taps, e + i) -> g_syn ----------------
#define TB3 128
#define SMEM3 (((TB3 + TNO) * SUB * 2 + TNO * SUB * 2) * (int)sizeof(float))  // 135168 B

__global__ void k3_conv() {
    extern __shared__ float sh[];
    float* se_sh = sh;
    float* si_sh = se_sh + (TB3 + TNO) * SUB;
    float* ke_sh = si_sh + (TB3 + TNO) * SUB;
    float* ki_sh = ke_sh + TNO * SUB;

    int t0 = blockIdx.x * TB3;

    for (int l = threadIdx.x; l < (TB3 + TNO) * SUB; l += blockDim.x) {
        int g = t0 - TNO + (l >> 5);
        bool ok = (g >= 0) && (g < T_DATA);
        size_t gi = (size_t)g * SUB + (l & 31);
        se_sh[l] = ok ? g_syn_e[gi] : 0.f;
        si_sh[l] = ok ? g_syn_i[gi] : 0.f;
    }
    for (int l = threadIdx.x; l < TNO * SUB; l += blockDim.x) {
        ke_sh[l] = g_ke[l];
        ki_sh[l] = g_ki[l];
    }
    __syncthreads();

    int lane = threadIdx.x & 31, wp = threadIdx.x >> 5;
    const float* seL = se_sh + lane;
    const float* siL = si_sh + lane;
    const float* keL = ke_sh + lane;
    const float* kiL = ki_sh + lane;

    for (int ob = wp * 16; ob < wp * 16 + 16; ob += 4) {
        float a0 = 0.f, a1 = 0.f, a2 = 0.f, a3 = 0.f;
        for (int tb = 0; tb < TNO; tb += 4) {
            int r0 = ob + TNO - 4 - tb;            // ob + 196 - tb
            const float* kp = keL + tb * SUB;
            const float* qp = kiL + tb * SUB;
            const float* sp = seL + r0 * SUB;
            const float* up = siL + r0 * SUB;

            float k0 = kp[0*SUB], k1 = kp[1*SUB], k2 = kp[2*SUB], k3 = kp[3*SUB];
            float s0 = sp[0*SUB], s1 = sp[1*SUB], s2 = sp[2*SUB], s3 = sp[3*SUB];
            float s4 = sp[4*SUB], s5 = sp[5*SUB], s6 = sp[6*SUB];

            a0 = fmaf(k0,s3,a0); a0 = fmaf(k1,s2,a0); a0 = fmaf(k2,s1,a0); a0 = fmaf(k3,s0,a0);
            a1 = fmaf(k0,s4,a1); a1 = fmaf(k1,s3,a1); a1 = fmaf(k2,s2,a1); a1 = fmaf(k3,s1,a1);
            a2 = fmaf(k0,s5,a2); a2 = fmaf(k1,s4,a2); a2 = fmaf(k2,s3,a2); a2 = fmaf(k3,s2,a2);
            a3 = fmaf(k0,s6,a3); a3 = fmaf(k1,s5,a3); a3 = fmaf(k2,s4,a3); a3 = fmaf(k3,s3,a3);

            float q0 = qp[0*SUB], q1 = qp[1*SUB], q2 = qp[2*SUB], q3 = qp[3*SUB];
            float u0 = up[0*SUB], u1 = up[1*SUB], u2 = up[2*SUB], u3 = up[3*SUB];
            float u4 = up[4*SUB], u5 = up[5*SUB], u6 = up[6*SUB];

            a0 = fmaf(q0,u3,a0); a0 = fmaf(q1,u2,a0); a0 = fmaf(q2,u1,a0); a0 = fmaf(q3,u0,a0);
            a1 = fmaf(q0,u4,a1); a1 = fmaf(q1,u3,a1); a1 = fmaf(q2,u2,a1); a1 = fmaf(q3,u1,a1);
            a2 = fmaf(q0,u5,a2); a2 = fmaf(q1,u4,a2); a2 = fmaf(q2,u3,a2); a2 = fmaf(q3,u2,a2);
            a3 = fmaf(q0,u6,a3); a3 = fmaf(q1,u5,a3); a3 = fmaf(q2,u4,a3); a3 = fmaf(q3,u3,a3);
        }
        int tg = t0 + ob;
        if (tg + 0 < T_DATA) g_syn[(size_t)(tg+0)*SUB + lane] = a0;
        if (tg + 1 < T_DATA) g_syn[(size_t)(tg+1)*SUB + lane] = a1;
        if (tg + 2 < T_DATA) g_syn[(size_t)(tg+2)*SUB + lane] = a2;
        if (tg + 3 < T_DATA) g_syn[(size_t)(tg+3)*SUB + lane] = a3;
    }
}

// ---------------- K4: hist filter + tree walk + heaviside -> Z_out ----------------
__global__ void __launch_bounds__(256) k4_tree(const float* __restrict__ Z,
                                               const float* __restrict__ Theta,
                                               float* __restrict__ dout) {
    __shared__ float Zsh[256 + TNO];
    __shared__ float hk[TNO];
    __shared__ float Cw[SUB * SUB];
    __shared__ float Th[SUB];

    int t0 = blockIdx.x * 256;
    for (int l = threadIdx.x; l < 256 + TNO; l += 256) {
        int g = t0 - TNO + l;
        Zsh[l] = (g >= 0 && g < T_DATA) ? Z[g] : 0.f;
    }
    for (int l = threadIdx.x; l < TNO; l += 256) hk[l] = g_hk[l];
    for (int l = threadIdx.x; l < SUB * SUB; l += 256) Cw[l] = g_cw[l];
    if (threadIdx.x < SUB) Th[threadIdx.x] = Theta[threadIdx.x];
    __syncthreads();

    int t = t0 + threadIdx.x;
    if (t >= T_DATA) return;

    float hist = 0.f;
    int tl = threadIdx.x;
    #pragma unroll 4
    for (int tau = 0; tau < TNO; tau++)
        hist = fmaf(hk[tau], Zsh[tl + TNO - 1 - tau], hist);

    float sy[SUB];
    const float4* sp = (const float4*)(g_syn + (size_t)t * SUB);
    #pragma unroll
    for (int i = 0; i < 8; i++) {
        float4 v = sp[i];
        sy[i*4+0] = v.x; sy[i*4+1] = v.y; sy[i*4+2] = v.z; sy[i*4+3] = v.w;
    }

    float sub[SUB];
    #pragma unroll
    for (int j = 0; j < SUB; j++) sub[j] = 0.f;

    #pragma unroll
    for (int idx = SUB - 1; idx >= 1; idx--) {
        float a = sy[idx] + Th[idx];
        #pragma unroll
        for (int j = 0; j < SUB; j++) a = fmaf(Cw[idx*SUB + j], sub[j], a);
        sub[idx] = tanhf(a);
    }

    float leaf = 0.f;
    #pragma unroll
    for (int j = 0; j < SUB; j++) leaf = fmaf(Cw[j], sub[j], leaf);

    float zin = hist + sy[0] + leaf + Th[0];
    dout[T_DATA + t] = (zin > 0.f) ? 1.f : 0.f;
}

// ---------------- K5: output alpha-kernel conv of Z_out -> V_out ----------------
__global__ void k5_vout(float* __restrict__ dout) {
    __shared__ float Zsh[256 + TNO];
    __shared__ float ok[TNO];
    const float* zo = dout + T_DATA;

    int t0 = blockIdx.x * 256;
    for (int l = threadIdx.x; l < 256 + TNO; l += 256) {
        int g = t0 - TNO + l;
        Zsh[l] = (g >= 0 && g < T_DATA) ? zo[g] : 0.f;
    }
    for (int l = threadIdx.x; l < TNO; l += 256) ok[l] = g_ok[l];
    __syncthreads();

    int t = t0 + threadIdx.x;
    if (t >= T_DATA) return;

    float v = 0.f;
    int tl = threadIdx.x;
    #pragma unroll 4
    for (int tau = 0; tau < TNO; tau++)
        v = fmaf(ok[tau], Zsh[tl + TNO - 1 - tau], v);
    dout[t] = v;
}

// ---------------- launcher ----------------
extern "C" void kernel_launch(void* const* d_in, const int* in_sizes, int n_in,
                              void* d_out, int out_size) {
    const float* Se        = (const float*)d_in[0];
    const float* Si        = (const float*)d_in[1];
    const float* Z         = (const float*)d_in[2];
    const float* Cden      = (const float*)d_in[3];
    const float* Ce        = (const float*)d_in[4];
    const float* Ci        = (const float*)d_in[5];
    const float* Tau_syn   = (const float*)d_in[6];
    const float* Delta_syn = (const float*)d_in[7];
    const float* W_syn     = (const float*)d_in[8];
    const float* W_sub     = (const float*)d_in[9];
    const float* W_hist    = (const float*)d_in[10];
    const float* Theta     = (const float*)d_in[11];
    const float* Tau_out   = (const float*)d_in[12];
    const float* W_out     = (const float*)d_in[13];
    float* out = (float*)d_out;

    k0_csr<<<(E_E + 255) / 256, 256>>>(Ce, Ci);
    k2_kernels<<<32, 256>>>(Tau_syn, Delta_syn, W_syn, W_sub, W_hist, Tau_out, W_out, Cden, out);
    k1_proj<<<(T_DATA + 7) / 8, 256>>>(Se, Si);

    cudaFuncSetAttribute(k3_conv, cudaFuncAttributeMaxDynamicSharedMemorySize, SMEM3);
    k3_conv<<<(T_DATA + TB3 - 1) / TB3, 256, SMEM3>>>();

    k4_tree<<<(T_DATA + 255) / 256, 256>>>(Z, Theta, out);
    k5_vout<<<(T_DATA + 255) / 256, 256>>>(out);
}

// round 2
// speedup vs baseline: 1.2285x; 1.2285x over previous
#include <cuda_runtime.h>
#include <math.h>

#define T_DATA 40000
#define SUB    32
#define E_E    2000
#define E_I    400
#define TNO    200
#define NCOS   17
#define FILT_OFF (2*T_DATA)

#define PI_F   3.14159274f      // float32(pi), matches jnp
#define HPI_F  1.5707964f       // float32(pi/2)

// ---------------- scratch (no allocation allowed) ----------------
__device__ float g_syn_e[(size_t)T_DATA*SUB];
__device__ float g_syn_i[(size_t)T_DATA*SUB];
__device__ float g_syn  [(size_t)T_DATA*SUB];
__device__ float g_ke[TNO*SUB];   // transposed [tau][s]
__device__ float g_ki[TNO*SUB];
__device__ float g_hk[TNO];
__device__ float g_ok[TNO];
__device__ int   g_ecnt[E_E];
__device__ int   g_esub[E_E*SUB];
__device__ float g_ew  [E_E*SUB];
__device__ int   g_icnt[E_I];
__device__ int   g_isub[E_I*SUB];
__device__ float g_iw  [E_I*SUB];
__device__ int   g_ch_cnt[SUB];
__device__ int   g_ch_idx[SUB*SUB];
__device__ float g_ch_w[SUB*SUB];

// ---------------- kS: setup — zero accumulators, CSR, kernels, children ----------------
__global__ void kS_setup(const float* __restrict__ Ce, const float* __restrict__ Ci,
                         const float* __restrict__ Tau_syn, const float* __restrict__ Delta_syn,
                         const float* __restrict__ W_syn,   const float* __restrict__ W_sub,
                         const float* __restrict__ W_hist,  const float* __restrict__ Tau_out,
                         const float* __restrict__ W_out,   const float* __restrict__ C_den,
                         float* __restrict__ dout) {
    int gid = blockIdx.x * blockDim.x + threadIdx.x;
    int nth = gridDim.x * blockDim.x;

    // zero atomic accumulators (must happen every replay!)
    float4 z4 = make_float4(0.f, 0.f, 0.f, 0.f);
    float4* ze = (float4*)g_syn_e;
    float4* zi = (float4*)g_syn_i;
    for (int i = gid; i < T_DATA*SUB/4; i += nth) { ze[i] = z4; zi[i] = z4; }

    // per-column CSR of C_syn_e / C_syn_i
    for (int e = gid; e < E_E; e += nth) {
        int c = 0;
        for (int s = 0; s < SUB; s++) {
            float w = Ce[(size_t)s * E_E + e];
            if (w != 0.f) { g_esub[e*SUB + c] = s; g_ew[e*SUB + c] = w; c++; }
        }
        g_ecnt[e] = c;
    }
    for (int e = gid; e < E_I; e += nth) {
        int c = 0;
        for (int s = 0; s < SUB; s++) {
            float w = Ci[(size_t)s * E_I + e];
            if (w != 0.f) { g_isub[e*SUB + c] = s; g_iw[e*SUB + c] = w; c++; }
        }
        g_icnt[e] = c;
    }

    // alpha kernels (transposed [tau][s]) + out_filters rows
    for (int i = gid; i < SUB * TNO; i += nth) {
        int s = i / TNO, tau = i % TNO;
        float t = (float)tau;
        float te  = fmaxf(t - expf(Delta_syn[s*2 + 0]), 0.f);
        float tte = te / expf(Tau_syn[s*2 + 0]);
        float ek  = tte * expf(-tte) * expf(W_syn[s*2 + 0]);
        float ti  = fmaxf(t - expf(Delta_syn[s*2 + 1]), 0.f);
        float tti = ti / expf(Tau_syn[s*2 + 1]);
        float ik  = -tti * expf(-tti) * expf(W_syn[s*2 + 1]);
        g_ke[tau*SUB + s] = ek;
        g_ki[tau*SUB + s] = ik;
        dout[FILT_OFF + s*TNO + tau]           = ek;
        dout[FILT_OFF + SUB*TNO + s*TNO + tau] = ik;
    }

    // history + output kernels
    for (int tau = gid; tau < TNO; tau += nth) {
        float raw = 4.f * logf((float)tau + 1.f);
        float hk = 0.f;
        #pragma unroll
        for (int n = 0; n < NCOS; n++) {
            float phi = HPI_F * (float)n;
            if (raw >= phi - PI_F && raw <= phi + PI_F)
                hk -= expf(W_hist[n]) * (0.5f * cosf(raw - phi) + 0.5f);
        }
        g_hk[tau] = hk;
        dout[FILT_OFF + 2*SUB*TNO + tau] = hk;

        float tto = (float)tau / expf(Tau_out[0]);
        g_ok[tau] = tto * expf(-tto) * expf(W_out[0]);
    }

    // children lists of the dendrite matrix (weights pre-multiplied by exp(W_sub))
    for (int p = gid; p < SUB; p += nth) {
        int c = 0;
        for (int j = 0; j < SUB; j++) {
            float w = C_den[p*SUB + j];
            if (w != 0.f) {
                g_ch_idx[p*SUB + c] = j;
                g_ch_w[p*SUB + c]   = w * expf(W_sub[j]);
                c++;
            }
        }
        g_ch_cnt[p] = c;
    }
}

// ---------------- K1: streaming sparse projection via global RED atomics ----------------
__global__ void __launch_bounds__(256) k1_proj(const float* __restrict__ Se,
                                               const float* __restrict__ Si) {
    int gt  = blockIdx.x * blockDim.x + threadIdx.x;
    int nth = gridDim.x * blockDim.x;

    // excitatory: 20M quads, 500 quads per row
    {
        const float4* p = (const float4*)Se;
        const int NQ = T_DATA * (E_E/4);
        for (int b = gt*4; b < NQ; b += nth*4) {
            float4 v0 = p[b+0], v1 = p[b+1], v2 = p[b+2], v3 = p[b+3];
            #pragma unroll
            for (int j = 0; j < 4; j++) {
                float4 q = (j==0) ? v0 : (j==1) ? v1 : (j==2) ? v2 : v3;
                if (q.x != 0.f || q.y != 0.f || q.z != 0.f || q.w != 0.f) {
                    int qi = b + j;
                    int t  = qi / 500;
                    int e0 = (qi - t*500) * 4;
                    float* dst = g_syn_e + (size_t)t * SUB;
                    if (q.x != 0.f) { int c = g_ecnt[e0+0]; for (int k=0;k<c;k++) atomicAdd(dst + g_esub[(e0+0)*SUB+k], q.x * g_ew[(e0+0)*SUB+k]); }
                    if (q.y != 0.f) { int c = g_ecnt[e0+1]; for (int k=0;k<c;k++) atomicAdd(dst + g_esub[(e0+1)*SUB+k], q.y * g_ew[(e0+1)*SUB+k]); }
                    if (q.z != 0.f) { int c = g_ecnt[e0+2]; for (int k=0;k<c;k++) atomicAdd(dst + g_esub[(e0+2)*SUB+k], q.z * g_ew[(e0+2)*SUB+k]); }
                    if (q.w != 0.f) { int c = g_ecnt[e0+3]; for (int k=0;k<c;k++) atomicAdd(dst + g_esub[(e0+3)*SUB+k], q.w * g_ew[(e0+3)*SUB+k]); }
                }
            }
        }
    }
    // inhibitory: 4M quads, 100 quads per row
    {
        const float4* p = (const float4*)Si;
        const int NQ = T_DATA * (E_I/4);
        for (int b = gt*4; b < NQ; b += nth*4) {
            float4 v0 = p[b+0], v1 = p[b+1], v2 = p[b+2], v3 = p[b+3];
            #pragma unroll
            for (int j = 0; j < 4; j++) {
                float4 q = (j==0) ? v0 : (j==1) ? v1 : (j==2) ? v2 : v3;
                if (q.x != 0.f || q.y != 0.f || q.z != 0.f || q.w != 0.f) {
                    int qi = b + j;
                    int t  = qi / 100;
                    int e0 = (qi - t*100) * 4;
                    float* dst = g_syn_i + (size_t)t * SUB;
                    if (q.x != 0.f) { int c = g_icnt[e0+0]; for (int k=0;k<c;k++) atomicAdd(dst + g_isub[(e0+0)*SUB+k], q.x * g_iw[(e0+0)*SUB+k]); }
                    if (q.y != 0.f) { int c = g_icnt[e0+1]; for (int k=0;k<c;k++) atomicAdd(dst + g_isub[(e0+1)*SUB+k], q.y * g_iw[(e0+1)*SUB+k]); }
                    if (q.z != 0.f) { int c = g_icnt[e0+2]; for (int k=0;k<c;k++) atomicAdd(dst + g_isub[(e0+2)*SUB+k], q.z * g_iw[(e0+2)*SUB+k]); }
                    if (q.w != 0.f) { int c = g_icnt[e0+3]; for (int k=0;k<c;k++) atomicAdd(dst + g_isub[(e0+3)*SUB+k], q.w * g_iw[(e0+3)*SUB+k]); }
                }
            }
        }
    }
}

// ---------------- K3: depthwise causal conv via fma.rn.f32x2 ----------------
__device__ __forceinline__ void ffma2(unsigned long long& d,
                                      unsigned long long a, unsigned long long b) {
    asm("fma.rn.f32x2 %0, %1, %2, %0;" : "+l"(d) : "l"(a), "l"(b));
}

#define TB3   256
#define ROWS3 (TB3 + TNO)                      // 456
#define SMEM3 (ROWS3 * SUB * 2 * (int)sizeof(float))  // 116736 B

__global__ void __launch_bounds__(512) k3_conv() {
    extern __shared__ float sh[];
    float* se_sh = sh;                   // [ROWS3][32]
    float* si_sh = sh + ROWS3 * SUB;

    int t0 = blockIdx.x * TB3;

    // tile load (float4, contiguous rows)
    {
        const float4* ge = (const float4*)g_syn_e;
        const float4* gi = (const float4*)g_syn_i;
        float4* de = (float4*)se_sh;
        float4* di = (float4*)si_sh;
        float4 z = make_float4(0.f, 0.f, 0.f, 0.f);
        for (int l = threadIdx.x; l < ROWS3 * 8; l += 512) {
            int row = l >> 3, c = l & 7;
            int g = t0 - TNO + row;
            if (g >= 0 && g < T_DATA) { de[l] = ge[g*8 + c]; di[l] = gi[g*8 + c]; }
            else                      { de[l] = z;           di[l] = z;           }
        }
    }
    __syncthreads();

    int lane  = threadIdx.x & 31, wid = threadIdx.x >> 5;
    int p     = lane & 15;               // channel pair (ch 2p, 2p+1)
    int tslot = lane >> 4;
    int ob    = wid * 16 + tslot * 8;    // output-time base within block

    const unsigned long long* se2 = (const unsigned long long*)se_sh;
    const unsigned long long* si2 = (const unsigned long long*)si_sh;
    const unsigned long long* ke2 = (const unsigned long long*)g_ke;
    const unsigned long long* ki2 = (const unsigned long long*)g_ki;

    unsigned long long acc[8];
    #pragma unroll
    for (int i = 0; i < 8; i++) acc[i] = 0ull;

    for (int tb = 0; tb < TNO; tb += 8) {
        int rbase = ob + 192 - tb;       // tile row for m = 0
        unsigned long long kk[8], ss[15];

        // excitatory signal
        #pragma unroll
        for (int j = 0; j < 8; j++) kk[j] = __ldg(&ke2[(tb + j)*16 + p]);
        #pragma unroll
        for (int m = 0; m < 15; m++) ss[m] = se2[(rbase + m)*16 + p];
        #pragma unroll
        for (int i = 0; i < 8; i++)
            #pragma unroll
            for (int j = 0; j < 8; j++)
                ffma2(acc[i], kk[j], ss[7 + i - j]);

        // inhibitory signal
        #pragma unroll
        for (int j = 0; j < 8; j++) kk[j] = __ldg(&ki2[(tb + j)*16 + p]);
        #pragma unroll
        for (int m = 0; m < 15; m++) ss[m] = si2[(rbase + m)*16 + p];
        #pragma unroll
        for (int i = 0; i < 8; i++)
            #pragma unroll
            for (int j = 0; j < 8; j++)
                ffma2(acc[i], kk[j], ss[7 + i - j]);
    }

    unsigned long long* out2 = (unsigned long long*)g_syn;
    #pragma unroll
    for (int i = 0; i < 8; i++) {
        int t = t0 + ob + i;
        if (t < T_DATA) out2[(size_t)t*16 + p] = acc[i];
    }
}

// ---------------- K4: hist filter + sparse tree walk + heaviside -> Z_out ----------------
#define TB4 256
#define SMEM4 ((SUB*TB4*2 + (TB4+TNO) + TNO + SUB) * (int)sizeof(float))  // 68288 B

__global__ void __launch_bounds__(TB4) k4_tree(const float* __restrict__ Z,
                                               const float* __restrict__ Theta,
                                               float* __restrict__ dout) {
    extern __shared__ float sh[];
    float* sub_sh = sh;                       // [node][tid]
    float* syn_sh = sub_sh + SUB*TB4;         // [node][tid]
    float* Zsh    = syn_sh + SUB*TB4;         // TB4 + TNO
    float* hk     = Zsh + (TB4 + TNO);        // TNO
    float* Th     = hk + TNO;                 // SUB

    int t0  = blockIdx.x * TB4;
    int tid = threadIdx.x;

    for (int l = tid; l < TB4 + TNO; l += TB4) {
        int g = t0 - TNO + l;
        Zsh[l] = (g >= 0 && g < T_DATA) ? Z[g] : 0.f;
    }
    for (int l = tid; l < TNO; l += TB4) hk[l] = g_hk[l];
    if (tid < SUB) Th[tid] = Theta[tid];

    int t = t0 + tid;
    if (t < T_DATA) {
        const float4* sp = (const float4*)(g_syn + (size_t)t * SUB);
        #pragma unroll
        for (int i = 0; i < 8; i++) {
            float4 v = sp[i];
            syn_sh[(i*4+0)*TB4 + tid] = v.x;
            syn_sh[(i*4+1)*TB4 + tid] = v.y;
            syn_sh[(i*4+2)*TB4 + tid] = v.z;
            syn_sh[(i*4+3)*TB4 + tid] = v.w;
        }
    }
    __syncthreads();
    if (t >= T_DATA) return;

    float hist = 0.f;
    #pragma unroll 4
    for (int tau = 0; tau < TNO; tau++)
        hist = fmaf(hk[tau], Zsh[tid + TNO - 1 - tau], hist);

    for (int idx = SUB - 1; idx >= 1; --idx) {
        float a = syn_sh[idx*TB4 + tid] + Th[idx];
        int c = g_ch_cnt[idx];
        for (int k = 0; k < c; k++) {
            int ci = g_ch_idx[idx*SUB + k];
            a = fmaf(g_ch_w[idx*SUB + k], sub_sh[ci*TB4 + tid], a);
        }
        sub_sh[idx*TB4 + tid] = tanhf(a);
    }

    float leaf = 0.f;
    {
        int c = g_ch_cnt[0];
        for (int k = 0; k < c; k++)
            leaf = fmaf(g_ch_w[k], sub_sh[g_ch_idx[k]*TB4 + tid], leaf);
    }

    float zin = hist + syn_sh[tid] + leaf + Th[0];
    dout[T_DATA + t] = (zin > 0.f) ? 1.f : 0.f;
}

// ---------------- K5: output alpha-kernel conv of Z_out -> V_out ----------------
__global__ void k5_vout(float* __restrict__ dout) {
    __shared__ float Zsh[256 + TNO];
    __shared__ float ok[TNO];
    const float* zo = dout + T_DATA;

    int t0 = blockIdx.x * 256;
    for (int l = threadIdx.x; l < 256 + TNO; l += 256) {
        int g = t0 - TNO + l;
        Zsh[l] = (g >= 0 && g < T_DATA) ? zo[g] : 0.f;
    }
    for (int l = threadIdx.x; l < TNO; l += 256) ok[l] = g_ok[l];
    __syncthreads();

    int t = t0 + threadIdx.x;
    if (t >= T_DATA) return;

    float v = 0.f;
    int tl = threadIdx.x;
    #pragma unroll 4
    for (int tau = 0; tau < TNO; tau++)
        v = fmaf(ok[tau], Zsh[tl + TNO - 1 - tau], v);
    dout[t] = v;
}

// ---------------- launcher ----------------
extern "C" void kernel_launch(void* const* d_in, const int* in_sizes, int n_in,
                              void* d_out, int out_size) {
    const float* Se        = (const float*)d_in[0];
    const float* Si        = (const float*)d_in[1];
    const float* Z         = (const float*)d_in[2];
    const float* Cden      = (const float*)d_in[3];
    const float* Ce        = (const float*)d_in[4];
    const float* Ci        = (const float*)d_in[5];
    const float* Tau_syn   = (const float*)d_in[6];
    const float* Delta_syn = (const float*)d_in[7];
    const float* W_syn     = (const float*)d_in[8];
    const float* W_sub     = (const float*)d_in[9];
    const float* W_hist    = (const float*)d_in[10];
    const float* Theta     = (const float*)d_in[11];
    const float* Tau_out   = (const float*)d_in[12];
    const float* W_out     = (const float*)d_in[13];
    float* out = (float*)d_out;

    kS_setup<<<1024, 256>>>(Ce, Ci, Tau_syn, Delta_syn, W_syn, W_sub, W_hist,
                            Tau_out, W_out, Cden, out);
    k1_proj<<<2048, 256>>>(Se, Si);

    cudaFuncSetAttribute(k3_conv, cudaFuncAttributeMaxDynamicSharedMemorySize, SMEM3);
    k3_conv<<<(T_DATA + TB3 - 1) / TB3, 512, SMEM3>>>();

    cudaFuncSetAttribute(k4_tree, cudaFuncAttributeMaxDynamicSharedMemorySize, SMEM4);
    k4_tree<<<(T_DATA + TB4 - 1) / TB4, TB4, SMEM4>>>(Z, Theta, out);

    k5_vout<<<(T_DATA + 255) / 256, 256>>>(out);
}

// round 3
// speedup vs baseline: 1.4430x; 1.1745x over previous
#include <cuda_runtime.h>
#include <math.h>

#define T_DATA 40000
#define SUB    32
#define E_E    2000
#define E_I    400
#define TNO    200
#define NCOS   17
#define FILT_OFF (2*T_DATA)

#define PI_F   3.14159274f      // float32(pi), matches jnp
#define HPI_F  1.5707964f       // float32(pi/2)

// ---------------- scratch (no allocation allowed) ----------------
__device__ float g_syn_e[(size_t)T_DATA*SUB];
__device__ float g_syn_i[(size_t)T_DATA*SUB];
__device__ float g_syn  [(size_t)T_DATA*SUB];
__device__ float g_ke[TNO*SUB];   // transposed [tau][s]
__device__ float g_ki[TNO*SUB];
__device__ float g_hk[TNO];
__device__ float g_ok[TNO];
// CSR tables in COLUMN-MAJOR layout: entry k of column e at [k*E + e].
// With mostly-one-hot columns the hot slice (k=0) is contiguous and L1-resident.
__device__ int   g_ecnt[E_E];
__device__ int   g_esub[SUB*E_E];
__device__ float g_ew  [SUB*E_E];
__device__ int   g_icnt[E_I];
__device__ int   g_isub[SUB*E_I];
__device__ float g_iw  [SUB*E_I];
__device__ int   g_ch_cnt[SUB];
__device__ int   g_ch_idx[SUB*SUB];
__device__ float g_ch_w[SUB*SUB];

// ---------------- kZ: zero the atomic accumulators (every replay) ----------------
__global__ void kZ_zero() {
    int gid = blockIdx.x * blockDim.x + threadIdx.x;
    int nth = gridDim.x * blockDim.x;
    float4 z4 = make_float4(0.f, 0.f, 0.f, 0.f);
    float4* ze = (float4*)g_syn_e;
    float4* zi = (float4*)g_syn_i;
    for (int i = gid; i < T_DATA*SUB/4; i += nth) { ze[i] = z4; zi[i] = z4; }
}

// ---------------- kC: CSR (column-major) + dendrite children lists ----------------
__global__ void kC_csr(const float* __restrict__ Ce, const float* __restrict__ Ci,
                       const float* __restrict__ C_den, const float* __restrict__ W_sub) {
    int e = blockIdx.x * blockDim.x + threadIdx.x;
    if (e < E_E) {
        int c = 0;
        for (int s = 0; s < SUB; s++) {
            float w = Ce[(size_t)s * E_E + e];
            if (w != 0.f) { g_esub[c*E_E + e] = s; g_ew[c*E_E + e] = w; c++; }
        }
        g_ecnt[e] = c;
    }
    if (e < E_I) {
        int c = 0;
        for (int s = 0; s < SUB; s++) {
            float w = Ci[(size_t)s * E_I + e];
            if (w != 0.f) { g_isub[c*E_I + e] = s; g_iw[c*E_I + e] = w; c++; }
        }
        g_icnt[e] = c;
    }
    if (e < SUB) {   // children lists, weights pre-multiplied by exp(W_sub[child])
        int c = 0;
        for (int j = 0; j < SUB; j++) {
            float w = C_den[e*SUB + j];
            if (w != 0.f) {
                g_ch_idx[e*SUB + c] = j;
                g_ch_w[e*SUB + c]   = w * expf(W_sub[j]);
                c++;
            }
        }
        g_ch_cnt[e] = c;
    }
}

// ---------------- kK: alpha/hist/out kernels + out_filters section of dout ----------------
__global__ void kK_kernels(const float* __restrict__ Tau_syn, const float* __restrict__ Delta_syn,
                           const float* __restrict__ W_syn,   const float* __restrict__ W_hist,
                           const float* __restrict__ Tau_out, const float* __restrict__ W_out,
                           float* __restrict__ dout) {
    int gid = blockIdx.x * blockDim.x + threadIdx.x;
    int nth = gridDim.x * blockDim.x;

    for (int i = gid; i < SUB * TNO; i += nth) {
        int s = i / TNO, tau = i % TNO;
        float t = (float)tau;
        float te  = fmaxf(t - expf(Delta_syn[s*2 + 0]), 0.f);
        float tte = te / expf(Tau_syn[s*2 + 0]);
        float ek  = tte * expf(-tte) * expf(W_syn[s*2 + 0]);
        float ti  = fmaxf(t - expf(Delta_syn[s*2 + 1]), 0.f);
        float tti = ti / expf(Tau_syn[s*2 + 1]);
        float ik  = -tti * expf(-tti) * expf(W_syn[s*2 + 1]);
        g_ke[tau*SUB + s] = ek;
        g_ki[tau*SUB + s] = ik;
        dout[FILT_OFF + s*TNO + tau]           = ek;
        dout[FILT_OFF + SUB*TNO + s*TNO + tau] = ik;
    }

    for (int tau = gid; tau < TNO; tau += nth) {
        float raw = 4.f * logf((float)tau + 1.f);
        float hk = 0.f;
        #pragma unroll
        for (int n = 0; n < NCOS; n++) {
            float phi = HPI_F * (float)n;
            if (raw >= phi - PI_F && raw <= phi + PI_F)
                hk -= expf(W_hist[n]) * (0.5f * cosf(raw - phi) + 0.5f);
        }
        g_hk[tau] = hk;
        dout[FILT_OFF + 2*SUB*TNO + tau] = hk;

        float tto = (float)tau / expf(Tau_out[0]);
        g_ok[tau] = tto * expf(-tto) * expf(W_out[0]);
    }
}

// ---------------- K1: streaming sparse projection (coalesced, MLP=4, L1-hot tables) ----------------
__device__ __forceinline__ void proc_quad(unsigned x, unsigned y, unsigned z, unsigned w,
                                          int qi, int rowq, int E,
                                          const int* __restrict__ cnt,
                                          const int* __restrict__ subi,
                                          const float* __restrict__ wt,
                                          float* __restrict__ base) {
    if ((x | y | z | w) == 0u) return;
    unsigned t  = (unsigned)qi / (unsigned)rowq;
    int      e0 = (qi - (int)t * rowq) * 4;
    float* dst = base + (size_t)t * SUB;
    if (x) { float f = __uint_as_float(x); int c = cnt[e0+0]; for (int k=0;k<c;k++) atomicAdd(dst + subi[k*E + e0+0], f * wt[k*E + e0+0]); }
    if (y) { float f = __uint_as_float(y); int c = cnt[e0+1]; for (int k=0;k<c;k++) atomicAdd(dst + subi[k*E + e0+1], f * wt[k*E + e0+1]); }
    if (z) { float f = __uint_as_float(z); int c = cnt[e0+2]; for (int k=0;k<c;k++) atomicAdd(dst + subi[k*E + e0+2], f * wt[k*E + e0+2]); }
    if (w) { float f = __uint_as_float(w); int c = cnt[e0+3]; for (int k=0;k<c;k++) atomicAdd(dst + subi[k*E + e0+3], f * wt[k*E + e0+3]); }
}

__global__ void __launch_bounds__(256) k1_proj(const float* __restrict__ Se,
                                               const float* __restrict__ Si) {
    int gt  = blockIdx.x * blockDim.x + threadIdx.x;
    int nth = gridDim.x * blockDim.x;

    // excitatory: 20M quads as 4 streams of 5M (MLP=4, lane-contiguous)
    {
        const uint4* p = (const uint4*)Se;
        const int Q4 = T_DATA * (E_E/4) / 4;   // 5,000,000
        for (int q = gt; q < Q4; q += nth) {
            uint4 v0 = p[q];
            uint4 v1 = p[q +   Q4];
            uint4 v2 = p[q + 2*Q4];
            uint4 v3 = p[q + 3*Q4];
            proc_quad(v0.x,v0.y,v0.z,v0.w, q,        500, E_E, g_ecnt, g_esub, g_ew, g_syn_e);
            proc_quad(v1.x,v1.y,v1.z,v1.w, q+Q4,     500, E_E, g_ecnt, g_esub, g_ew, g_syn_e);
            proc_quad(v2.x,v2.y,v2.z,v2.w, q+2*Q4,   500, E_E, g_ecnt, g_esub, g_ew, g_syn_e);
            proc_quad(v3.x,v3.y,v3.z,v3.w, q+3*Q4,   500, E_E, g_ecnt, g_esub, g_ew, g_syn_e);
        }
    }
    // inhibitory: 4M quads as 4 streams of 1M
    {
        const uint4* p = (const uint4*)Si;
        const int Q4 = T_DATA * (E_I/4) / 4;   // 1,000,000
        for (int q = gt; q < Q4; q += nth) {
            uint4 v0 = p[q];
            uint4 v1 = p[q +   Q4];
            uint4 v2 = p[q + 2*Q4];
            uint4 v3 = p[q + 3*Q4];
            proc_quad(v0.x,v0.y,v0.z,v0.w, q,        100, E_I, g_icnt, g_isub, g_iw, g_syn_i);
            proc_quad(v1.x,v1.y,v1.z,v1.w, q+Q4,     100, E_I, g_icnt, g_isub, g_iw, g_syn_i);
            proc_quad(v2.x,v2.y,v2.z,v2.w, q+2*Q4,   100, E_I, g_icnt, g_isub, g_iw, g_syn_i);
            proc_quad(v3.x,v3.y,v3.z,v3.w, q+3*Q4,   100, E_I, g_icnt, g_isub, g_iw, g_syn_i);
        }
    }
}

// ---------------- K3: depthwise causal conv via fma.rn.f32x2 ----------------
__device__ __forceinline__ void ffma2(unsigned long long& d,
                                      unsigned long long a, unsigned long long b) {
    asm("fma.rn.f32x2 %0, %1, %2, %0;" : "+l"(d) : "l"(a), "l"(b));
}

#define TB3   256
#define ROWS3 (TB3 + TNO)                      // 456
#define SMEM3 (ROWS3 * SUB * 2 * (int)sizeof(float))  // 116736 B

__global__ void __launch_bounds__(512) k3_conv() {
    extern __shared__ float sh[];
    float* se_sh = sh;                   // [ROWS3][32]
    float* si_sh = sh + ROWS3 * SUB;

    int t0 = blockIdx.x * TB3;

    {
        const float4* ge = (const float4*)g_syn_e;
        const float4* gi = (const float4*)g_syn_i;
        float4* de = (float4*)se_sh;
        float4* di = (float4*)si_sh;
        float4 z = make_float4(0.f, 0.f, 0.f, 0.f);
        for (int l = threadIdx.x; l < ROWS3 * 8; l += 512) {
            int row = l >> 3, c = l & 7;
            int g = t0 - TNO + row;
            if (g >= 0 && g < T_DATA) { de[l] = ge[g*8 + c]; di[l] = gi[g*8 + c]; }
            else                      { de[l] = z;           di[l] = z;           }
        }
    }
    __syncthreads();

    int lane  = threadIdx.x & 31, wid = threadIdx.x >> 5;
    int p     = lane & 15;               // channel pair (ch 2p, 2p+1)
    int tslot = lane >> 4;
    int ob    = wid * 16 + tslot * 8;    // output-time base within block

    const unsigned long long* se2 = (const unsigned long long*)se_sh;
    const unsigned long long* si2 = (const unsigned long long*)si_sh;
    const unsigned long long* ke2 = (const unsigned long long*)g_ke;
    const unsigned long long* ki2 = (const unsigned long long*)g_ki;

    unsigned long long acc[8];
    #pragma unroll
    for (int i = 0; i < 8; i++) acc[i] = 0ull;

    for (int tb = 0; tb < TNO; tb += 8) {
        int rbase = ob + 192 - tb;
        unsigned long long kk[8], ss[15];

        #pragma unroll
        for (int j = 0; j < 8; j++) kk[j] = __ldg(&ke2[(tb + j)*16 + p]);
        #pragma unroll
        for (int m = 0; m < 15; m++) ss[m] = se2[(rbase + m)*16 + p];
        #pragma unroll
        for (int i = 0; i < 8; i++)
            #pragma unroll
            for (int j = 0; j < 8; j++)
                ffma2(acc[i], kk[j], ss[7 + i - j]);

        #pragma unroll
        for (int j = 0; j < 8; j++) kk[j] = __ldg(&ki2[(tb + j)*16 + p]);
        #pragma unroll
        for (int m = 0; m < 15; m++) ss[m] = si2[(rbase + m)*16 + p];
        #pragma unroll
        for (int i = 0; i < 8; i++)
            #pragma unroll
            for (int j = 0; j < 8; j++)
                ffma2(acc[i], kk[j], ss[7 + i - j]);
    }

    unsigned long long* out2 = (unsigned long long*)g_syn;
    #pragma unroll
    for (int i = 0; i < 8; i++) {
        int t = t0 + ob + i;
        if (t < T_DATA) out2[(size_t)t*16 + p] = acc[i];
    }
}

// ---------------- K4: hist filter + sparse tree walk + heaviside -> Z_out ----------------
#define TB4 256
#define SMEM4 ((SUB*TB4*2 + (TB4+TNO) + TNO + SUB) * (int)sizeof(float))  // 68288 B

__global__ void __launch_bounds__(TB4) k4_tree(const float* __restrict__ Z,
                                               const float* __restrict__ Theta,
                                               float* __restrict__ dout) {
    extern __shared__ float sh[];
    float* sub_sh = sh;                       // [node][tid]
    float* syn_sh = sub_sh + SUB*TB4;         // [node][tid]
    float* Zsh    = syn_sh + SUB*TB4;         // TB4 + TNO
    float* hk     = Zsh + (TB4 + TNO);        // TNO
    float* Th     = hk + TNO;                 // SUB

    int t0  = blockIdx.x * TB4;
    int tid = threadIdx.x;

    for (int l = tid; l < TB4 + TNO; l += TB4) {
        int g = t0 - TNO + l;
        Zsh[l] = (g >= 0 && g < T_DATA) ? Z[g] : 0.f;
    }
    for (int l = tid; l < TNO; l += TB4) hk[l] = g_hk[l];
    if (tid < SUB) Th[tid] = Theta[tid];

    int t = t0 + tid;
    if (t < T_DATA) {
        const float4* sp = (const float4*)(g_syn + (size_t)t * SUB);
        #pragma unroll
        for (int i = 0; i < 8; i++) {
            float4 v = sp[i];
            syn_sh[(i*4+0)*TB4 + tid] = v.x;
            syn_sh[(i*4+1)*TB4 + tid] = v.y;
            syn_sh[(i*4+2)*TB4 + tid] = v.z;
            syn_sh[(i*4+3)*TB4 + tid] = v.w;
        }
    }
    __syncthreads();
    if (t >= T_DATA) return;

    float hist = 0.f;
    #pragma unroll 4
    for (int tau = 0; tau < TNO; tau++)
        hist = fmaf(hk[tau], Zsh[tid + TNO - 1 - tau], hist);

    for (int idx = SUB - 1; idx >= 1; --idx) {
        float a = syn_sh[idx*TB4 + tid] + Th[idx];
        int c = g_ch_cnt[idx];
        for (int k = 0; k < c; k++) {
            int ci = g_ch_idx[idx*SUB + k];
            a = fmaf(g_ch_w[idx*SUB + k], sub_sh[ci*TB4 + tid], a);
        }
        sub_sh[idx*TB4 + tid] = tanhf(a);
    }

    float leaf = 0.f;
    {
        int c = g_ch_cnt[0];
        for (int k = 0; k < c; k++)
            leaf = fmaf(g_ch_w[k], sub_sh[g_ch_idx[k]*TB4 + tid], leaf);
    }

    float zin = hist + syn_sh[tid] + leaf + Th[0];
    dout[T_DATA + t] = (zin > 0.f) ? 1.f : 0.f;
}

// ---------------- K5: output alpha-kernel conv of Z_out -> V_out ----------------
__global__ void k5_vout(float* __restrict__ dout) {
    __shared__ float Zsh[256 + TNO];
    __shared__ float ok[TNO];
    const float* zo = dout + T_DATA;

    int t0 = blockIdx.x * 256;
    for (int l = threadIdx.x; l < 256 + TNO; l += 256) {
        int g = t0 - TNO + l;
        Zsh[l] = (g >= 0 && g < T_DATA) ? zo[g] : 0.f;
    }
    for (int l = threadIdx.x; l < TNO; l += 256) ok[l] = g_ok[l];
    __syncthreads();

    int t = t0 + threadIdx.x;
    if (t >= T_DATA) return;

    float v = 0.f;
    int tl = threadIdx.x;
    #pragma unroll 4
    for (int tau = 0; tau < TNO; tau++)
        v = fmaf(ok[tau], Zsh[tl + TNO - 1 - tau], v);
    dout[t] = v;
}

// ---------------- launcher ----------------
extern "C" void kernel_launch(void* const* d_in, const int* in_sizes, int n_in,
                              void* d_out, int out_size) {
    const float* Se        = (const float*)d_in[0];
    const float* Si        = (const float*)d_in[1];
    const float* Z         = (const float*)d_in[2];
    const float* Cden      = (const float*)d_in[3];
    const float* Ce        = (const float*)d_in[4];
    const float* Ci        = (const float*)d_in[5];
    const float* Tau_syn   = (const float*)d_in[6];
    const float* Delta_syn = (const float*)d_in[7];
    const float* W_syn     = (const float*)d_in[8];
    const float* W_sub     = (const float*)d_in[9];
    const float* W_hist    = (const float*)d_in[10];
    const float* Theta     = (const float*)d_in[11];
    const float* Tau_out   = (const float*)d_in[12];
    const float* W_out     = (const float*)d_in[13];
    float* out = (float*)d_out;

    kZ_zero<<<512, 256>>>();
    kC_csr<<<(E_E + 255) / 256, 256>>>(Ce, Ci, Cden, W_sub);
    kK_kernels<<<32, 256>>>(Tau_syn, Delta_syn, W_syn, W_hist, Tau_out, W_out, out);
    k1_proj<<<1024, 256>>>(Se, Si);     // 4th launch -> ncu capture slot

    cudaFuncSetAttribute(k3_conv, cudaFuncAttributeMaxDynamicSharedMemorySize, SMEM3);
    k3_conv<<<(T_DATA + TB3 - 1) / TB3, 512, SMEM3>>>();

    cudaFuncSetAttribute(k4_tree, cudaFuncAttributeMaxDynamicSharedMemorySize, SMEM4);
    k4_tree<<<(T_DATA + TB4 - 1) / TB4, TB4, SMEM4>>>(Z, Theta, out);

    k5_vout<<<(T_DATA + 255) / 256, 256>>>(out);
}

// round 4
// speedup vs baseline: 1.6266x; 1.1273x over previous
#include <cuda_runtime.h>
#include <math.h>

#define T_DATA 40000
#define SUB    32
#define E_E    2000
#define E_I    400
#define TNO    200
#define NCOS   17
#define FILT_OFF (2*T_DATA)

#define PI_F   3.14159274f      // float32(pi), matches jnp
#define HPI_F  1.5707964f       // float32(pi/2)

// ---------------- scratch (no allocation allowed) ----------------
__device__ float g_syn_e[(size_t)T_DATA*SUB];
__device__ float g_syn_i[(size_t)T_DATA*SUB];
__device__ float g_syn  [(size_t)T_DATA*SUB];
__device__ float g_ke[TNO*SUB];   // transposed [tau][s]
__device__ float g_ki[TNO*SUB];
__device__ float g_hk[TNO];
__device__ float g_ok[TNO];
// one-hot fast tables: {byte_offset = s*4, float_bits(w)} per column
__device__ int2  g_etab[E_E];
__device__ int2  g_itab[E_I];
__device__ int   g_onehot;
// generic fallback CSR (row-major, cold)
__device__ int   g_ecnt[E_E];
__device__ int   g_esub[E_E*SUB];
__device__ float g_ew  [E_E*SUB];
__device__ int   g_icnt[E_I];
__device__ int   g_isub[E_I*SUB];
__device__ float g_iw  [E_I*SUB];
__device__ int   g_ch_cnt[SUB];
__device__ int   g_ch_idx[SUB*SUB];
__device__ float g_ch_w[SUB*SUB];

// ---------------- kZ: zero accumulators + reset one-hot flag (every replay) ----------------
__global__ void kZ_zero() {
    int gid = blockIdx.x * blockDim.x + threadIdx.x;
    int nth = gridDim.x * blockDim.x;
    if (gid == 0) g_onehot = 1;
    float4 z4 = make_float4(0.f, 0.f, 0.f, 0.f);
    float4* ze = (float4*)g_syn_e;
    float4* zi = (float4*)g_syn_i;
    for (int i = gid; i < T_DATA*SUB/4; i += nth) { ze[i] = z4; zi[i] = z4; }
}

// ---------------- kC: fast tables + generic CSR + dendrite children ----------------
__global__ void kC_csr(const float* __restrict__ Ce, const float* __restrict__ Ci,
                       const float* __restrict__ C_den, const float* __restrict__ W_sub) {
    int e = blockIdx.x * blockDim.x + threadIdx.x;
    if (e < E_E) {
        int c = 0; int s0 = 0; float w0 = 0.f;
        for (int s = 0; s < SUB; s++) {
            float w = Ce[(size_t)s * E_E + e];
            if (w != 0.f) {
                if (c == 0) { s0 = s; w0 = w; }
                g_esub[e*SUB + c] = s; g_ew[e*SUB + c] = w; c++;
            }
        }
        g_ecnt[e] = c;
        g_etab[e] = make_int2(s0 * 4, __float_as_int(w0));
        if (c > 1) atomicAnd(&g_onehot, 0);
    }
    if (e < E_I) {
        int c = 0; int s0 = 0; float w0 = 0.f;
        for (int s = 0; s < SUB; s++) {
            float w = Ci[(size_t)s * E_I + e];
            if (w != 0.f) {
                if (c == 0) { s0 = s; w0 = w; }
                g_isub[e*SUB + c] = s; g_iw[e*SUB + c] = w; c++;
            }
        }
        g_icnt[e] = c;
        g_itab[e] = make_int2(s0 * 4, __float_as_int(w0));
        if (c > 1) atomicAnd(&g_onehot, 0);
    }
    if (e < SUB) {   // children lists, weights pre-multiplied by exp(W_sub[child])
        int c = 0;
        for (int j = 0; j < SUB; j++) {
            float w = C_den[e*SUB + j];
            if (w != 0.f) {
                g_ch_idx[e*SUB + c] = j;
                g_ch_w[e*SUB + c]   = w * expf(W_sub[j]);
                c++;
            }
        }
        g_ch_cnt[e] = c;
    }
}

// ---------------- kK: alpha/hist/out kernels + out_filters section of dout ----------------
__global__ void kK_kernels(const float* __restrict__ Tau_syn, const float* __restrict__ Delta_syn,
                           const float* __restrict__ W_syn,   const float* __restrict__ W_hist,
                           const float* __restrict__ Tau_out, const float* __restrict__ W_out,
                           float* __restrict__ dout) {
    int gid = blockIdx.x * blockDim.x + threadIdx.x;
    int nth = gridDim.x * blockDim.x;

    for (int i = gid; i < SUB * TNO; i += nth) {
        int s = i / TNO, tau = i % TNO;
        float t = (float)tau;
        float te  = fmaxf(t - expf(Delta_syn[s*2 + 0]), 0.f);
        float tte = te / expf(Tau_syn[s*2 + 0]);
        float ek  = tte * expf(-tte) * expf(W_syn[s*2 + 0]);
        float ti  = fmaxf(t - expf(Delta_syn[s*2 + 1]), 0.f);
        float tti = ti / expf(Tau_syn[s*2 + 1]);
        float ik  = -tti * expf(-tti) * expf(W_syn[s*2 + 1]);
        g_ke[tau*SUB + s] = ek;
        g_ki[tau*SUB + s] = ik;
        dout[FILT_OFF + s*TNO + tau]           = ek;
        dout[FILT_OFF + SUB*TNO + s*TNO + tau] = ik;
    }

    for (int tau = gid; tau < TNO; tau += nth) {
        float raw = 4.f * logf((float)tau + 1.f);
        float hk = 0.f;
        #pragma unroll
        for (int n = 0; n < NCOS; n++) {
            float phi = HPI_F * (float)n;
            if (raw >= phi - PI_F && raw <= phi + PI_F)
                hk -= expf(W_hist[n]) * (0.5f * cosf(raw - phi) + 0.5f);
        }
        g_hk[tau] = hk;
        dout[FILT_OFF + 2*SUB*TNO + tau] = hk;

        float tto = (float)tau / expf(Tau_out[0]);
        g_ok[tau] = tto * expf(-tto) * expf(W_out[0]);
    }
}

// ---------------- K1: branch-free predicated spike scatter ----------------
// if (v != 0): {off,w} = *tab; red.global dst[off] += v*w  — no BSSY, masked lanes free.
__device__ __forceinline__ void spike_add(float v, const int2* tab, float* dst) {
    asm volatile(
        "{\n\t"
        ".reg .pred p;\n\t"
        ".reg .b32 ro, rw;\n\t"
        ".reg .f32 fw, fv;\n\t"
        ".reg .b64 ra;\n\t"
        "setp.ne.f32 p, %0, 0f00000000;\n\t"
        "@p ld.global.nc.v2.b32 {ro, rw}, [%1];\n\t"
        "@p cvt.u64.u32 ra, ro;\n\t"
        "@p add.s64 ra, ra, %2;\n\t"
        "@p mov.b32 fw, rw;\n\t"
        "@p mul.f32 fv, %0, fw;\n\t"
        "@p red.global.add.f32 [ra], fv;\n\t"
        "}" :: "f"(v), "l"(tab), "l"(dst) : "memory");
}

__global__ void __launch_bounds__(256) k1_proj(const float* __restrict__ Se,
                                               const float* __restrict__ Si) {
    int lane  = threadIdx.x & 31;
    int warp  = (blockIdx.x * blockDim.x + threadIdx.x) >> 5;
    int nwarp = (gridDim.x * blockDim.x) >> 5;

    // ---- excitatory: 20,000,000 quads (500/row), 128 quads per warp-step ----
    {
        const float4* p = (const float4*)Se;
        const int NQ = T_DATA * (E_E/4);           // 20,000,000 = 128 * 156250
        for (int wb = warp * 128; wb < NQ; wb += nwarp * 128) {
            int q0 = wb + lane, q1 = q0 + 32, q2 = q0 + 64, q3 = q0 + 96;
            float4 v0 = __ldg(p + q0);
            float4 v1 = __ldg(p + q1);
            float4 v2 = __ldg(p + q2);
            float4 v3 = __ldg(p + q3);
            #pragma unroll
            for (int j = 0; j < 4; j++) {
                int qi = (j==0) ? q0 : (j==1) ? q1 : (j==2) ? q2 : q3;
                float4 v = (j==0) ? v0 : (j==1) ? v1 : (j==2) ? v2 : v3;
                unsigned t = (unsigned)qi / 500u;
                int e0 = (qi - (int)t * 500) * 4;
                float* dst = g_syn_e + (size_t)t * SUB;
                const int2* tb = g_etab + e0;
                spike_add(v.x, tb + 0, dst);
                spike_add(v.y, tb + 1, dst);
                spike_add(v.z, tb + 2, dst);
                spike_add(v.w, tb + 3, dst);
            }
        }
    }
    // ---- inhibitory: 4,000,000 quads (100/row) ----
    {
        const float4* p = (const float4*)Si;
        const int NQ = T_DATA * (E_I/4);           // 4,000,000 = 128 * 31250
        for (int wb = warp * 128; wb < NQ; wb += nwarp * 128) {
            int q0 = wb + lane, q1 = q0 + 32, q2 = q0 + 64, q3 = q0 + 96;
            float4 v0 = __ldg(p + q0);
            float4 v1 = __ldg(p + q1);
            float4 v2 = __ldg(p + q2);
            float4 v3 = __ldg(p + q3);
            #pragma unroll
            for (int j = 0; j < 4; j++) {
                int qi = (j==0) ? q0 : (j==1) ? q1 : (j==2) ? q2 : q3;
                float4 v = (j==0) ? v0 : (j==1) ? v1 : (j==2) ? v2 : v3;
                unsigned t = (unsigned)qi / 100u;
                int e0 = (qi - (int)t * 100) * 4;
                float* dst = g_syn_i + (size_t)t * SUB;
                const int2* tb = g_itab + e0;
                spike_add(v.x, tb + 0, dst);
                spike_add(v.y, tb + 1, dst);
                spike_add(v.z, tb + 2, dst);
                spike_add(v.w, tb + 3, dst);
            }
        }
    }

    // ---- generic fallback for non-one-hot columns (never taken for this data) ----
    if (__ldg(&g_onehot) == 0) {
        int gt  = blockIdx.x * blockDim.x + threadIdx.x;
        int nth = gridDim.x * blockDim.x;
        for (int e = gt; e < E_E; e += nth) {
            int c = g_ecnt[e];
            if (c > 1) {
                for (int t = 0; t < T_DATA; t++) {
                    float v = Se[(size_t)t * E_E + e];
                    if (v != 0.f)
                        for (int k = 1; k < c; k++)
                            atomicAdd(g_syn_e + (size_t)t*SUB + g_esub[e*SUB+k], v * g_ew[e*SUB+k]);
                }
            }
        }
        for (int e = gt; e < E_I; e += nth) {
            int c = g_icnt[e];
            if (c > 1) {
                for (int t = 0; t < T_DATA; t++) {
                    float v = Si[(size_t)t * E_I + e];
                    if (v != 0.f)
                        for (int k = 1; k < c; k++)
                            atomicAdd(g_syn_i + (size_t)t*SUB + g_isub[e*SUB+k], v * g_iw[e*SUB+k]);
                }
            }
        }
    }
}

// ---------------- K3: depthwise causal conv via fma.rn.f32x2 ----------------
__device__ __forceinline__ void ffma2(unsigned long long& d,
                                      unsigned long long a, unsigned long long b) {
    asm("fma.rn.f32x2 %0, %1, %2, %0;" : "+l"(d) : "l"(a), "l"(b));
}

#define TB3   256
#define ROWS3 (TB3 + TNO)                      // 456
#define SMEM3 (ROWS3 * SUB * 2 * (int)sizeof(float))  // 116736 B

__global__ void __launch_bounds__(512) k3_conv() {
    extern __shared__ float sh[];
    float* se_sh = sh;                   // [ROWS3][32]
    float* si_sh = sh + ROWS3 * SUB;

    int t0 = blockIdx.x * TB3;

    {
        const float4* ge = (const float4*)g_syn_e;
        const float4* gi = (const float4*)g_syn_i;
        float4* de = (float4*)se_sh;
        float4* di = (float4*)si_sh;
        float4 z = make_float4(0.f, 0.f, 0.f, 0.f);
        for (int l = threadIdx.x; l < ROWS3 * 8; l += 512) {
            int row = l >> 3, c = l & 7;
            int g = t0 - TNO + row;
            if (g >= 0 && g < T_DATA) { de[l] = ge[g*8 + c]; di[l] = gi[g*8 + c]; }
            else                      { de[l] = z;           di[l] = z;           }
        }
    }
    __syncthreads();

    int lane  = threadIdx.x & 31, wid = threadIdx.x >> 5;
    int p     = lane & 15;               // channel pair (ch 2p, 2p+1)
    int tslot = lane >> 4;
    int ob    = wid * 16 + tslot * 8;    // output-time base within block

    const unsigned long long* se2 = (const unsigned long long*)se_sh;
    const unsigned long long* si2 = (const unsigned long long*)si_sh;
    const unsigned long long* ke2 = (const unsigned long long*)g_ke;
    const unsigned long long* ki2 = (const unsigned long long*)g_ki;

    unsigned long long acc[8];
    #pragma unroll
    for (int i = 0; i < 8; i++) acc[i] = 0ull;

    for (int tb = 0; tb < TNO; tb += 8) {
        int rbase = ob + 192 - tb;
        unsigned long long kk[8], ss[15];

        #pragma unroll
        for (int j = 0; j < 8; j++) kk[j] = __ldg(&ke2[(tb + j)*16 + p]);
        #pragma unroll
        for (int m = 0; m < 15; m++) ss[m] = se2[(rbase + m)*16 + p];
        #pragma unroll
        for (int i = 0; i < 8; i++)
            #pragma unroll
            for (int j = 0; j < 8; j++)
                ffma2(acc[i], kk[j], ss[7 + i - j]);

        #pragma unroll
        for (int j = 0; j < 8; j++) kk[j] = __ldg(&ki2[(tb + j)*16 + p]);
        #pragma unroll
        for (int m = 0; m < 15; m++) ss[m] = si2[(rbase + m)*16 + p];
        #pragma unroll
        for (int i = 0; i < 8; i++)
            #pragma unroll
            for (int j = 0; j < 8; j++)
                ffma2(acc[i], kk[j], ss[7 + i - j]);
    }

    unsigned long long* out2 = (unsigned long long*)g_syn;
    #pragma unroll
    for (int i = 0; i < 8; i++) {
        int t = t0 + ob + i;
        if (t < T_DATA) out2[(size_t)t*16 + p] = acc[i];
    }
}

// ---------------- K4: hist filter + sparse tree walk + heaviside -> Z_out ----------------
#define TB4 256
#define SMEM4 ((SUB*TB4*2 + (TB4+TNO) + TNO + SUB) * (int)sizeof(float))  // 68288 B

__global__ void __launch_bounds__(TB4) k4_tree(const float* __restrict__ Z,
                                               const float* __restrict__ Theta,
                                               float* __restrict__ dout) {
    extern __shared__ float sh[];
    float* sub_sh = sh;                       // [node][tid]
    float* syn_sh = sub_sh + SUB*TB4;         // [node][tid]
    float* Zsh    = syn_sh + SUB*TB4;         // TB4 + TNO
    float* hk     = Zsh + (TB4 + TNO);        // TNO
    float* Th     = hk + TNO;                 // SUB

    int t0  = blockIdx.x * TB4;
    int tid = threadIdx.x;

    for (int l = tid; l < TB4 + TNO; l += TB4) {
        int g = t0 - TNO + l;
        Zsh[l] = (g >= 0 && g < T_DATA) ? Z[g] : 0.f;
    }
    for (int l = tid; l < TNO; l += TB4) hk[l] = g_hk[l];
    if (tid < SUB) Th[tid] = Theta[tid];

    int t = t0 + tid;
    if (t < T_DATA) {
        const float4* sp = (const float4*)(g_syn + (size_t)t * SUB);
        #pragma unroll
        for (int i = 0; i < 8; i++) {
            float4 v = sp[i];
            syn_sh[(i*4+0)*TB4 + tid] = v.x;
            syn_sh[(i*4+1)*TB4 + tid] = v.y;
            syn_sh[(i*4+2)*TB4 + tid] = v.z;
            syn_sh[(i*4+3)*TB4 + tid] = v.w;
        }
    }
    __syncthreads();
    if (t >= T_DATA) return;

    float hist = 0.f;
    #pragma unroll 4
    for (int tau = 0; tau < TNO; tau++)
        hist = fmaf(hk[tau], Zsh[tid + TNO - 1 - tau], hist);

    for (int idx = SUB - 1; idx >= 1; --idx) {
        float a = syn_sh[idx*TB4 + tid] + Th[idx];
        int c = g_ch_cnt[idx];
        for (int k = 0; k < c; k++) {
            int ci = g_ch_idx[idx*SUB + k];
            a = fmaf(g_ch_w[idx*SUB + k], sub_sh[ci*TB4 + tid], a);
        }
        sub_sh[idx*TB4 + tid] = tanhf(a);
    }

    float leaf = 0.f;
    {
        int c = g_ch_cnt[0];
        for (int k = 0; k < c; k++)
            leaf = fmaf(g_ch_w[k], sub_sh[g_ch_idx[k]*TB4 + tid], leaf);
    }

    float zin = hist + syn_sh[tid] + leaf + Th[0];
    dout[T_DATA + t] = (zin > 0.f) ? 1.f : 0.f;
}

// ---------------- K5: output alpha-kernel conv of Z_out -> V_out ----------------
__global__ void k5_vout(float* __restrict__ dout) {
    __shared__ float Zsh[256 + TNO];
    __shared__ float ok[TNO];
    const float* zo = dout + T_DATA;

    int t0 = blockIdx.x * 256;
    for (int l = threadIdx.x; l < 256 + TNO; l += 256) {
        int g = t0 - TNO + l;
        Zsh[l] = (g >= 0 && g < T_DATA) ? zo[g] : 0.f;
    }
    for (int l = threadIdx.x; l < TNO; l += 256) ok[l] = g_ok[l];
    __syncthreads();

    int t = t0 + threadIdx.x;
    if (t >= T_DATA) return;

    float v = 0.f;
    int tl = threadIdx.x;
    #pragma unroll 4
    for (int tau = 0; tau < TNO; tau++)
        v = fmaf(ok[tau], Zsh[tl + TNO - 1 - tau], v);
    dout[t] = v;
}

// ---------------- launcher ----------------
extern "C" void kernel_launch(void* const* d_in, const int* in_sizes, int n_in,
                              void* d_out, int out_size) {
    const float* Se        = (const float*)d_in[0];
    const float* Si        = (const float*)d_in[1];
    const float* Z         = (const float*)d_in[2];
    const float* Cden      = (const float*)d_in[3];
    const float* Ce        = (const float*)d_in[4];
    const float* Ci        = (const float*)d_in[5];
    const float* Tau_syn   = (const float*)d_in[6];
    const float* Delta_syn = (const float*)d_in[7];
    const float* W_syn     = (const float*)d_in[8];
    const float* W_sub     = (const float*)d_in[9];
    const float* W_hist    = (const float*)d_in[10];
    const float* Theta     = (const float*)d_in[11];
    const float* Tau_out   = (const float*)d_in[12];
    const float* W_out     = (const float*)d_in[13];
    float* out = (float*)d_out;

    kZ_zero<<<512, 256>>>();
    kC_csr<<<(E_E + 255) / 256, 256>>>(Ce, Ci, Cden, W_sub);
    kK_kernels<<<32, 256>>>(Tau_syn, Delta_syn, W_syn, W_hist, Tau_out, W_out, out);
    k1_proj<<<2048, 256>>>(Se, Si);     // 4th launch -> ncu capture slot

    cudaFuncSetAttribute(k3_conv, cudaFuncAttributeMaxDynamicSharedMemorySize, SMEM3);
    k3_conv<<<(T_DATA + TB3 - 1) / TB3, 512, SMEM3>>>();

    cudaFuncSetAttribute(k4_tree, cudaFuncAttributeMaxDynamicSharedMemorySize, SMEM4);
    k4_tree<<<(T_DATA + TB4 - 1) / TB4, TB4, SMEM4>>>(Z, Theta, out);

    k5_vout<<<(T_DATA + 255) / 256, 256>>>(out);
}